// round 16
// baseline (speedup 1.0000x reference)
#include <cuda_runtime.h>
#include <cuda_fp16.h>

#define NN 100000
#define NE 1200000
#define D 64
#define NL 3
#define NG 256
#define RH 128
#define RO 32
#define INDIM (D*NL)   // 192
#define GR 64          // rows per GEMM block
#define MAXD 64        // padded neighbor-bucket capacity (Poisson(12): safe)

typedef unsigned long long ull;

// ---------------- scratch (device globals; no allocation allowed) ----------
__device__ int     d_deg[NN];
__device__ int     d_col2[NN * MAXD];   // padded adjacency buckets (25.6 MB)
__device__ float   d_h0[NN * D];
__device__ float   d_h1[NN * D];
__device__ __half2 d_yh[NN * (D / 2)];  // fp16 GEMM output, 128B rows
__device__ float   d_g[NG * INDIM];

// ---------------- f32x2 helpers -------------------------------------------
static __device__ __forceinline__ ull pk2(float x, float y) {
    ull r; asm("mov.b64 %0, {%1, %2};" : "=l"(r) : "f"(x), "f"(y)); return r;
}
static __device__ __forceinline__ void upk2(ull v, float& x, float& y) {
    asm("mov.b64 {%0, %1}, %2;" : "=f"(x), "=f"(y) : "l"(v));
}
static __device__ __forceinline__ void ffma2(ull& c, ull a, ull b) {
    asm("fma.rn.f32x2 %0, %1, %2, %0;" : "+l"(c) : "l"(a), "l"(b));
}
static __device__ __forceinline__ void acc_h2pair(float4& acc, uint2 v) {
    __half2 h0 = *reinterpret_cast<__half2*>(&v.x);
    __half2 h1 = *reinterpret_cast<__half2*>(&v.y);
    float2 f0 = __half22float2(h0);
    float2 f1 = __half22float2(h1);
    acc.x += f0.x; acc.y += f0.y; acc.z += f1.x; acc.w += f1.y;
}

// ---------------- one-pass bucket CSR --------------------------------------
__global__ void k_scatter(const int* __restrict__ src, const int* __restrict__ dst) {
    int e = blockIdx.x * blockDim.x + threadIdx.x;
    if (e < NE) {
        int dn = dst[e];
        int p = atomicAdd(&d_deg[dn], 1);
        if (p < MAXD) d_col2[(dn << 6) + p] = src[e];
    }
}

__global__ void k_zerog() {
    int i = blockIdx.x * blockDim.x + threadIdx.x;
    if (i < NG * INDIM) d_g[i] = 0.0f;
}

// ---------------- dense GEMM: Yh = fp16(Hin @ W[layer]) (R11 core) ---------
__global__ void __launch_bounds__(256) k_gemm(
    const float* __restrict__ Hin, __half2* __restrict__ Yh,
    const float* __restrict__ gin_W, int layer)
{
    __shared__ float4 Zs[GR][16];     // 64 rows x 64 floats (16 KB)
    __shared__ float2 Wsp[D][32];     // W[k][dp] pairs (16 KB)

    int tid = threadIdx.x;
    int row0 = blockIdx.x * GR;

    const float4* Wg = (const float4*)(gin_W + layer * D * D);
    float4* Ws4 = (float4*)&Wsp[0][0];
#pragma unroll
    for (int i = 0; i < 4; i++) Ws4[tid + 256 * i] = Wg[tid + 256 * i];

    const float4* Hg = (const float4*)Hin;
#pragma unroll
    for (int i = 0; i < 4; i++) {
        int idx = tid + 256 * i;
        int r = row0 + (idx >> 4);
        int rc = (r < NN) ? r : (NN - 1);
        Zs[idx >> 4][idx & 15] = Hg[(size_t)rc * 16 + (idx & 15)];
    }
    __syncthreads();

    int dp = tid & 31;
    int rg = tid >> 5;

    ull accA[8], accB[8];
#pragma unroll
    for (int n = 0; n < 8; n++) { accA[n] = 0ull; accB[n] = 0ull; }

    for (int kc = 0; kc < D; kc += 16) {
        ull wA[8], wB[8];
#pragma unroll
        for (int p = 0; p < 8; p++) {
            float2 lo = Wsp[kc + 2 * p][dp];
            float2 hi = Wsp[kc + 2 * p + 1][dp];
            wA[p] = pk2(lo.x, hi.x);
            wB[p] = pk2(lo.y, hi.y);
        }
#pragma unroll
        for (int n = 0; n < 8; n++) {
            const ull* zrowU = (const ull*)&Zs[rg * 8 + n][0];
#pragma unroll
            for (int q = 0; q < 4; q++) {
                ull zA = zrowU[kc / 2 + 2 * q];
                ull zB = zrowU[kc / 2 + 2 * q + 1];
                ffma2(accA[n], wA[2 * q],     zA);
                ffma2(accB[n], wB[2 * q],     zA);
                ffma2(accA[n], wA[2 * q + 1], zB);
                ffma2(accB[n], wB[2 * q + 1], zB);
            }
        }
    }

#pragma unroll
    for (int n = 0; n < 8; n++) {
        int r = row0 + rg * 8 + n;
        if (r < NN) {
            float ax, ay, bx, by;
            upk2(accA[n], ax, ay);
            upk2(accB[n], bx, by);
            Yh[(size_t)r * 32 + dp] = __floats2half2_rn(ax + ay, bx + by);
        }
    }
}

// ---------------- fused aggregation + per-graph readout -------------------
// 16 lanes per node (2 nodes/warp); lane owns dims 4gl..4gl+3 as fp16 pairs.
// Warp-uniform loop bound keeps shfl converged; fp32 accumulation.
__global__ void __launch_bounds__(256) k_agg(
    const __half2* __restrict__ Yh, float* __restrict__ hout,
    const float* __restrict__ gin_b, const float* __restrict__ eps,
    const int* __restrict__ gids, int layer)
{
    __shared__ float sm[16][D];
    __shared__ int sg[16];

    int tid = threadIdx.x;
    int lane = tid & 31;
    int gl = lane & 15;              // lane within 16-group
    int base = lane & 16;            // 0 low half, 16 high half
    int grp = tid >> 4;              // node group within block
    int node = blockIdx.x * 16 + grp;   // NN % 16 == 0

    float epsv = 1.0f + eps[layer];
    const float4* b4 = (const float4*)(gin_b + layer * D);
    float4 bv = b4[gl];

    const uint2* Yu = (const uint2*)Yh;   // 16 uint2 per 128B row

    float4 acc = make_float4(0.f, 0.f, 0.f, 0.f);
    acc_h2pair(acc, Yu[(size_t)node * 16 + gl]);
    acc.x *= epsv; acc.y *= epsv; acc.z *= epsv; acc.w *= epsv;

    int deg = min(d_deg[node], MAXD);
    int degMax = max(deg, __shfl_xor_sync(0xffffffffu, deg, 16));

    int4 iv = ((const int4*)&d_col2[node << 6])[gl];

    for (int j4 = 0; j4 < degMax; j4 += 4) {
        int slot = base + (j4 >> 2);
        int s0 = __shfl_sync(0xffffffffu, iv.x, slot);
        int s1 = __shfl_sync(0xffffffffu, iv.y, slot);
        int s2 = __shfl_sync(0xffffffffu, iv.z, slot);
        int s3 = __shfl_sync(0xffffffffu, iv.w, slot);
        int rem = deg - j4;          // may be <= 0 for this half-warp
        if (rem >= 4) {
            uint2 v0 = Yu[(size_t)s0 * 16 + gl];
            uint2 v1 = Yu[(size_t)s1 * 16 + gl];
            uint2 v2 = Yu[(size_t)s2 * 16 + gl];
            uint2 v3 = Yu[(size_t)s3 * 16 + gl];
            acc_h2pair(acc, v0);
            acc_h2pair(acc, v1);
            acc_h2pair(acc, v2);
            acc_h2pair(acc, v3);
        } else if (rem > 0) {
            acc_h2pair(acc, Yu[(size_t)s0 * 16 + gl]);
            if (rem > 1) acc_h2pair(acc, Yu[(size_t)s1 * 16 + gl]);
            if (rem > 2) acc_h2pair(acc, Yu[(size_t)s2 * 16 + gl]);
        }
    }

    float4 o;
    o.x = fmaxf(acc.x + bv.x, 0.0f);
    o.y = fmaxf(acc.y + bv.y, 0.0f);
    o.z = fmaxf(acc.z + bv.z, 0.0f);
    o.w = fmaxf(acc.w + bv.w, 0.0f);
    ((float4*)(hout + (size_t)node * D))[gl] = o;

    // epilogue: per-graph segment reduce of this block's 16 rows
    ((float4*)&sm[grp][0])[gl] = o;
    if (gl == 0) sg[grp] = gids[node];
    __syncthreads();

    if (tid < D) {
        int dd = tid;
        float run = 0.0f;
        int curg = sg[0];
#pragma unroll
        for (int n = 0; n < 16; n++) {
            int gn = sg[n];
            float v = sm[n][dd];
            if (gn != curg) {
                atomicAdd(&d_g[curg * INDIM + layer * D + dd], run);
                run = 0.0f;
                curg = gn;
            }
            run += v;
        }
        atomicAdd(&d_g[curg * INDIM + layer * D + dd], run);
    }
}

// ---------------- readout MLP ---------------------------------------------
__global__ void k_mlp(const float* __restrict__ W1, const float* __restrict__ b1,
                      const float* __restrict__ W2, const float* __restrict__ b2,
                      float* __restrict__ out)
{
    __shared__ float gv[INDIM];
    __shared__ float hid[RH];
    int b = blockIdx.x;
    int tid = threadIdx.x;   // 128 threads
    for (int i = tid; i < INDIM; i += RH) gv[i] = d_g[b * INDIM + i];
    __syncthreads();
    float a = b1[tid];
#pragma unroll 8
    for (int k = 0; k < INDIM; k++)
        a += gv[k] * W1[k * RH + tid];
    hid[tid] = fmaxf(a, 0.0f);
    __syncthreads();
    if (tid < RO) {
        float o = b2[tid];
#pragma unroll 8
        for (int k = 0; k < RH; k++)
            o += hid[k] * W2[k * RO + tid];
        out[b * RO + tid] = o;
    }
}

// ---------------- launch ---------------------------------------------------
extern "C" void kernel_launch(void* const* d_in, const int* in_sizes, int n_in,
                              void* d_out, int out_size)
{
    const float* x      = (const float*)d_in[0];
    const float* gin_W  = (const float*)d_in[1];
    const float* gin_b  = (const float*)d_in[2];
    const float* eps    = (const float*)d_in[3];
    const float* r_W1   = (const float*)d_in[4];
    const float* r_b1   = (const float*)d_in[5];
    const float* r_W2   = (const float*)d_in[6];
    const float* r_b2   = (const float*)d_in[7];
    const int*   src    = (const int*)d_in[8];
    const int*   dst    = (const int*)d_in[9];
    const int*   gids   = (const int*)d_in[10];
    float* out = (float*)d_out;

    static float*   h0p = nullptr;
    static float*   h1p = nullptr;
    static __half2* yhp = nullptr;
    static int*     degp = nullptr;
    if (!h0p) {
        cudaGetSymbolAddress((void**)&h0p, d_h0);
        cudaGetSymbolAddress((void**)&h1p, d_h1);
        cudaGetSymbolAddress((void**)&yhp, d_yh);
        cudaGetSymbolAddress((void**)&degp, d_deg);
    }

    cudaMemsetAsync(degp, 0, NN * sizeof(int));
    k_scatter<<<(NE + 255) / 256, 256>>>(src, dst);
    k_zerog<<<(NG * INDIM + 255) / 256, 256>>>();

    const float* hin = x;
    float* bufs[2] = { h0p, h1p };
    for (int l = 0; l < NL; l++) {
        float* hout = bufs[l & 1];
        k_gemm<<<(NN + GR - 1) / GR, 256>>>(hin, yhp, gin_W, l);
        k_agg<<<NN / 16, 256>>>(yhp, hout, gin_b, eps, gids, l);
        hin = hout;
    }

    k_mlp<<<NG, RH>>>(r_W1, r_b1, r_W2, r_b2, out);
}